// round 8
// baseline (speedup 1.0000x reference)
#include <cuda_runtime.h>
#include <cstdint>
#include <cstddef>

#define BT 256
#define TT 250
#define II 700
#define HH 128
#define OO 20

// Scratch: xin[b][t][h] = (x @ w_ih1 + b_ih1)
__device__ float g_xin[BT * TT * HH];
// layer-2 spike bit-words: [b][t][4] (bit j of word w = spike of h = w*32+j)
__device__ unsigned int g_spk[BT * TT * 4];

// Correctly-rounded f32 exp: double exp (<=1.5 ulp in double) rounded to f32
// gives the correctly-rounded f32 result except astronomically rare cases.
// Matches glibc scalar expf (correctly rounded), unlike CUDA expf (<=2 ulp).
__device__ __forceinline__ float exp_cr(float x) {
    return (float)exp((double)x);
}

// packed f32x2 helpers
__device__ __forceinline__ unsigned long long pack2(float lo, float hi) {
    unsigned long long r;
    asm("mov.b64 %0, {%1, %2};" : "=l"(r) : "f"(lo), "f"(hi));
    return r;
}
__device__ __forceinline__ void unpack2(unsigned long long v, float& lo, float& hi) {
    asm("mov.b64 {%0, %1}, %2;" : "=f"(lo), "=f"(hi) : "l"(v));
}
__device__ __forceinline__ void ffma2(unsigned long long& d, unsigned long long a,
                                      unsigned long long b) {
    asm("fma.rn.f32x2 %0, %1, %2, %0;" : "+l"(d) : "l"(a), "l"(b));
}

// ---------------------------------------------------------------------------
// Kernel 1: xin = x @ w_ih1 + b_ih1 — FULL FP32, single ascending-k FMA chain
// per output (matches both cuBLAS sgemm and Eigen gebp accumulation order).
// ---------------------------------------------------------------------------
__global__ __launch_bounds__(256) void gemm_xin_kernel(
    const float* __restrict__ x, const float* __restrict__ w,
    const float* __restrict__ bias)
{
    __shared__ float a_sm[16][132];
    __shared__ float b_sm[16][128];

    const int tid = threadIdx.x;
    const int m0 = blockIdx.x * 128;
    const int tx = tid & 15, ty = tid >> 4;
    const int r0 = ty * 8, c0 = tx * 8;

    unsigned long long acc[8][4];
#pragma unroll
    for (int r = 0; r < 8; r++)
#pragma unroll
        for (int j = 0; j < 4; j++) acc[r][j] = 0ull;

    for (int k0 = 0; k0 < II; k0 += 16) {
#pragma unroll
        for (int p = 0; p < 8; p++) {
            int idx = tid + p * 256;
            int ml = idx >> 4, kl = idx & 15;
            int k = k0 + kl;
            a_sm[kl][ml] = (k < II) ? x[(size_t)(m0 + ml) * II + k] : 0.f;
        }
#pragma unroll
        for (int p = 0; p < 8; p++) {
            int idx = tid + p * 256;
            int kl = idx >> 7, hh = idx & 127;
            int k = k0 + kl;
            b_sm[kl][hh] = (k < II) ? w[k * HH + hh] : 0.f;
        }
        __syncthreads();
#pragma unroll
        for (int kk = 0; kk < 16; kk++) {
            float a[8];
            unsigned long long bb[4];
#pragma unroll
            for (int r = 0; r < 8; r++) a[r] = a_sm[kk][r0 + r];
            const float2* bp = reinterpret_cast<const float2*>(&b_sm[kk][c0]);
#pragma unroll
            for (int j = 0; j < 4; j++) { float2 v = bp[j]; bb[j] = pack2(v.x, v.y); }
#pragma unroll
            for (int r = 0; r < 8; r++) {
                unsigned long long ad = pack2(a[r], a[r]);
#pragma unroll
                for (int j = 0; j < 4; j++) ffma2(acc[r][j], ad, bb[j]);
            }
        }
        __syncthreads();
    }

#pragma unroll
    for (int r = 0; r < 8; r++) {
        int m = m0 + r0 + r;
#pragma unroll
        for (int j = 0; j < 4; j++) {
            float lo, hi;
            unpack2(acc[r][j], lo, hi);
            int c = c0 + 2 * j;
            float2 v;
            v.x = __fadd_rn(lo, bias[c]);
            v.y = __fadd_rn(hi, bias[c + 1]);
            *reinterpret_cast<float2*>(&g_xin[(size_t)m * HH + c]) = v;
        }
    }
}

// ---------------------------------------------------------------------------
// Kernel 2: the 250-step scan. 128 blocks x 128 thr (2 batch rows / block).
// Config A numerics (all fp32, exact association) + correctly-rounded exp
// for the decay constants.
// ---------------------------------------------------------------------------
#define SCAN_SMEM_FLOATS (3 * 16384 + 3 * 128 + 256 + 256)

__global__ __launch_bounds__(128) void scan_kernel(
    const float* __restrict__ mask,
    const float* __restrict__ w_h1h1, const float* __restrict__ b_h1h1,
    const float* __restrict__ w_h1h2, const float* __restrict__ b_h1h2,
    const float* __restrict__ w_h2h2, const float* __restrict__ b_h2h2,
    const float* __restrict__ tau_adp_h1, const float* __restrict__ tau_adp_h2,
    const float* __restrict__ tau_m_h1,   const float* __restrict__ tau_m_h2,
    const float* __restrict__ hid1_mem0, const float* __restrict__ hid2_mem0,
    float* __restrict__ out)
{
    extern __shared__ float sm[];
    float*  w11  = sm;                  // [k][h] masked, fp32
    float*  w12  = w11 + 16384;         // [k][h] fp32
    float*  w22  = w12 + 16384;         // [k][h] masked, fp32
    float*  b11s = w22 + 16384;
    float*  b12s = b11s + 128;
    float*  b22s = b12s + 128;
    float2* s1p  = (float2*)(b22s + 128);   // [128] {row0,row1}
    float2* s2p  = s1p + 128;               // [128]

    const int h  = threadIdx.x;
    const int b0 = blockIdx.x * 2;

#pragma unroll 4
    for (int k = 0; k < 128; k++) {
        int i = k * 128 + h;
        w11[i] = __fmul_rn(w_h1h1[i], mask[i]);
        w12[i] = w_h1h2[i];
        w22[i] = __fmul_rn(w_h2h2[i], mask[16384 + i]);
    }
    b11s[h] = b_h1h1[h];
    b12s[h] = b_h1h2[h];
    b22s[h] = b_h2h2[h];
    s1p[h] = make_float2(0.f, 0.f);
    s2p[h] = make_float2(0.f, 0.f);

    const float a1 = exp_cr(__fdiv_rn(-1.0f, tau_m_h1[h]));
    const float r1 = exp_cr(__fdiv_rn(-1.0f, tau_adp_h1[h]));
    const float a2 = exp_cr(__fdiv_rn(-1.0f, tau_m_h2[h]));
    const float r2 = exp_cr(__fdiv_rn(-1.0f, tau_adp_h2[h]));
    const float oma1 = __fsub_rn(1.f, a1);
    const float omr1 = __fsub_rn(1.f, r1);
    const float oma2 = __fsub_rn(1.f, a2);
    const float omr2 = __fsub_rn(1.f, r2);

    float h1m[2], h2m[2];
    float h1sp[2] = {0.f, 0.f}, h2sp[2] = {0.f, 0.f};
    float bb1[2] = {0.01f, 0.01f}, bb2[2] = {0.01f, 0.01f};
    float cnt1[2] = {0.f, 0.f}, cnt2[2] = {0.f, 0.f};
    h1m[0] = hid1_mem0[(size_t)b0 * 128 + h];
    h1m[1] = hid1_mem0[(size_t)(b0 + 1) * 128 + h];
    h2m[0] = hid2_mem0[(size_t)b0 * 128 + h];
    h2m[1] = hid2_mem0[(size_t)(b0 + 1) * 128 + h];

    const int wi = h >> 5;
    const int l  = h & 31;

    __syncthreads();

    const float* xin0 = g_xin + (size_t)b0 * TT * HH + h;
    const float* xin1 = g_xin + (size_t)(b0 + 1) * TT * HH + h;

    for (int t = 0; t < TT; t++) {
        // --- recurrent dots against previous-step spikes (ascending k) ---
        float m1a = 0.f, m1b = 0.f, m22a = 0.f, m22b = 0.f;
#pragma unroll 8
        for (int k = 0; k < 128; k++) {
            float2 sp1 = s1p[k];
            float2 sp2 = s2p[k];
            float wa = w11[k * 128 + h];
            float wb = w22[k * 128 + h];
            m1a  = __fmaf_rn(sp1.x, wa, m1a);
            m1b  = __fmaf_rn(sp1.y, wa, m1b);
            m22a = __fmaf_rn(sp2.x, wb, m22a);
            m22b = __fmaf_rn(sp2.y, wb, m22b);
        }
        // --- layer 1 update ---
        float i1a = __fadd_rn(__fadd_rn(xin0[(size_t)t * HH], m1a), b11s[h]);
        float i1b = __fadd_rn(__fadd_rn(xin1[(size_t)t * HH], m1b), b11s[h]);
        bb1[0] = __fadd_rn(__fmul_rn(r1, bb1[0]), __fmul_rn(omr1, h1sp[0]));
        bb1[1] = __fadd_rn(__fmul_rn(r1, bb1[1]), __fmul_rn(omr1, h1sp[1]));
        float B1a = __fadd_rn(0.01f, __fmul_rn(1.8f, bb1[0]));
        float B1b = __fadd_rn(0.01f, __fmul_rn(1.8f, bb1[1]));
        h1m[0] = __fsub_rn(__fadd_rn(__fmul_rn(h1m[0], a1), __fmul_rn(oma1, i1a)),
                           __fmul_rn(B1a, h1sp[0]));
        h1m[1] = __fsub_rn(__fadd_rn(__fmul_rn(h1m[1], a1), __fmul_rn(oma1, i1b)),
                           __fmul_rn(B1b, h1sp[1]));
        float s1n0 = (__fsub_rn(h1m[0], B1a) > 0.f) ? 1.f : 0.f;
        float s1n1 = (__fsub_rn(h1m[1], B1b) > 0.f) ? 1.f : 0.f;
        cnt1[0] += s1n0; cnt1[1] += s1n1;
        h1sp[0] = s1n0;  h1sp[1] = s1n1;
        __syncthreads();
        s1p[h] = make_float2(s1n0, s1n1);
        __syncthreads();
        // --- layer 2: uses NEW layer-1 spikes ---
        float m12a = 0.f, m12b = 0.f;
#pragma unroll 8
        for (int k = 0; k < 128; k++) {
            float2 sp = s1p[k];
            float w = w12[k * 128 + h];
            m12a = __fmaf_rn(sp.x, w, m12a);
            m12b = __fmaf_rn(sp.y, w, m12b);
        }
        float i2a = __fadd_rn(__fadd_rn(__fadd_rn(m12a, b12s[h]), m22a), b22s[h]);
        float i2b = __fadd_rn(__fadd_rn(__fadd_rn(m12b, b12s[h]), m22b), b22s[h]);
        bb2[0] = __fadd_rn(__fmul_rn(r2, bb2[0]), __fmul_rn(omr2, h2sp[0]));
        bb2[1] = __fadd_rn(__fmul_rn(r2, bb2[1]), __fmul_rn(omr2, h2sp[1]));
        float B2a = __fadd_rn(0.01f, __fmul_rn(1.8f, bb2[0]));
        float B2b = __fadd_rn(0.01f, __fmul_rn(1.8f, bb2[1]));
        h2m[0] = __fsub_rn(__fadd_rn(__fmul_rn(h2m[0], a2), __fmul_rn(oma2, i2a)),
                           __fmul_rn(B2a, h2sp[0]));
        h2m[1] = __fsub_rn(__fadd_rn(__fmul_rn(h2m[1], a2), __fmul_rn(oma2, i2b)),
                           __fmul_rn(B2b, h2sp[1]));
        float s2n0 = (__fsub_rn(h2m[0], B2a) > 0.f) ? 1.f : 0.f;
        float s2n1 = (__fsub_rn(h2m[1], B2b) > 0.f) ? 1.f : 0.f;
        cnt2[0] += s2n0; cnt2[1] += s2n1;
        h2sp[0] = s2n0;  h2sp[1] = s2n1;
        __syncthreads();
        s2p[h] = make_float2(s2n0, s2n1);
        // export layer-2 spikes as bit-words for the readout kernel
        unsigned int wrd0 = __ballot_sync(0xffffffffu, s2n0 != 0.f);
        unsigned int wrd1 = __ballot_sync(0xffffffffu, s2n1 != 0.f);
        if (l == 0) {
            g_spk[((size_t)b0 * TT + t) * 4 + wi]       = wrd0;
            g_spk[((size_t)(b0 + 1) * TT + t) * 4 + wi] = wrd1;
        }
        __syncthreads();
    }

    const float T250 = 250.0f;
    out[5120 + (size_t)b0 * 128 + h]               = cnt1[0] / T250;
    out[5120 + (size_t)(b0 + 1) * 128 + h]         = cnt1[1] / T250;
    out[5120 + 32768 + (size_t)b0 * 128 + h]       = cnt2[0] / T250;
    out[5120 + 32768 + (size_t)(b0 + 1) * 128 + h] = cnt2[1] / T250;
}

// ---------------------------------------------------------------------------
// Kernel 3: readout (om recursion + masked softmax accumulation), full fp32
// with correctly-rounded exp.
// ---------------------------------------------------------------------------
__global__ __launch_bounds__(128) void readout_kernel(
    const float* __restrict__ w_h2o, const float* __restrict__ b_h2o,
    const float* __restrict__ tau_m_o, const float* __restrict__ out_mem0,
    float* __restrict__ out)
{
    __shared__ float w2o_sm[128 * 20];
    __shared__ unsigned int spk[TT][4];
    __shared__ float io_sm[TT][20];

    const int b = blockIdx.x;
    const int tid = threadIdx.x;

    for (int i = tid; i < 128 * 20; i += 128) w2o_sm[i] = w_h2o[i];
    for (int i = tid; i < TT * 4; i += 128)
        ((unsigned int*)spk)[i] = g_spk[(size_t)b * TT * 4 + i];
    __syncthreads();

    for (int p = tid; p < TT * 20; p += 128) {
        int t = p / 20;
        int o = p - t * 20;
        float acc = 0.f;
#pragma unroll
        for (int w = 0; w < 4; w++) {
            unsigned int word = spk[t][w];
#pragma unroll
            for (int j = 0; j < 32; j++) {
                if (word & (1u << j))
                    acc = __fadd_rn(acc, w2o_sm[(w * 32 + j) * 20 + o]);
            }
        }
        io_sm[t][o] = acc;
    }
    __syncthreads();

    if (tid < 32) {
        const int ll = tid;
        float om = 0.f, ao = 0.f, bo = 0.f, accm = 0.f;
        if (ll < 20) {
            om = out_mem0[(size_t)b * 20 + ll];
            ao = (float)exp((double)__fdiv_rn(-1.0f, tau_m_o[ll]));
            bo = b_h2o[ll];
        }
        const float omao = __fsub_rn(1.f, ao);
        for (int t = 0; t < TT; t++) {
            float iov = (ll < 20) ? __fadd_rn(io_sm[t][ll], bo) : 0.f;
            om = __fadd_rn(__fmul_rn(om, ao), __fmul_rn(omao, iov));
            if (t > 10) {
                float v = (ll < 20) ? om : -3.402823466e38f;
#pragma unroll
                for (int d = 16; d > 0; d >>= 1)
                    v = fmaxf(v, __shfl_xor_sync(0xffffffffu, v, d));
                float e = (ll < 20) ? (float)exp((double)__fsub_rn(om, v)) : 0.f;
                float ssum = 0.f;
#pragma unroll
                for (int o = 0; o < 20; o++)
                    ssum = __fadd_rn(ssum, __shfl_sync(0xffffffffu, e, o));
                if (ll < 20) accm = __fadd_rn(accm, __fdiv_rn(e, ssum));
            }
        }
        if (ll < 20) out[(size_t)b * 20 + ll] = accm;
    }
}

// ---------------------------------------------------------------------------
// Kernel 4: A_norm (fp32 elementwise; sum|w11| and sum|w22| separately, then add)
// ---------------------------------------------------------------------------
__global__ __launch_bounds__(256) void anorm_kernel(
    const float* __restrict__ w_h1h1, const float* __restrict__ w_h2h2,
    const float* __restrict__ mask, float* __restrict__ out)
{
    __shared__ float red1[256];
    __shared__ float red2[256];
    int tid = threadIdx.x;
    float s1 = 0.f, s2 = 0.f;
    for (int i = tid; i < 16384; i += 256) {
        s1 = __fadd_rn(s1, fabsf(__fmul_rn(w_h1h1[i], mask[i])));
        s2 = __fadd_rn(s2, fabsf(__fmul_rn(w_h2h2[i], mask[16384 + i])));
    }
    red1[tid] = s1;
    red2[tid] = s2;
    __syncthreads();
#pragma unroll
    for (int st = 128; st > 0; st >>= 1) {
        if (tid < st) {
            red1[tid] = __fadd_rn(red1[tid], red1[tid + st]);
            red2[tid] = __fadd_rn(red2[tid], red2[tid + st]);
        }
        __syncthreads();
    }
    if (tid == 0) out[5120 + 2 * 32768] = __fadd_rn(red1[0], red2[0]);
}

// ---------------------------------------------------------------------------
extern "C" void kernel_launch(void* const* d_in, const int* in_sizes, int n_in,
                              void* d_out, int out_size)
{
    (void)in_sizes; (void)n_in; (void)out_size;
    const float* x          = (const float*)d_in[0];
    const float* mask       = (const float*)d_in[1];
    const float* w_ih1      = (const float*)d_in[2];
    const float* b_ih1      = (const float*)d_in[3];
    const float* w_h1h1     = (const float*)d_in[4];
    const float* b_h1h1     = (const float*)d_in[5];
    const float* w_h1h2     = (const float*)d_in[6];
    const float* b_h1h2     = (const float*)d_in[7];
    const float* w_h2h2     = (const float*)d_in[8];
    const float* b_h2h2     = (const float*)d_in[9];
    const float* w_h2o      = (const float*)d_in[10];
    const float* b_h2o      = (const float*)d_in[11];
    const float* tau_adp_h1 = (const float*)d_in[12];
    const float* tau_adp_h2 = (const float*)d_in[13];
    const float* tau_m_h1   = (const float*)d_in[14];
    const float* tau_m_h2   = (const float*)d_in[15];
    const float* tau_m_o    = (const float*)d_in[16];
    const float* hid1_mem0  = (const float*)d_in[17];
    const float* hid2_mem0  = (const float*)d_in[18];
    const float* out_mem0   = (const float*)d_in[19];
    float* out = (float*)d_out;

    gemm_xin_kernel<<<(BT * TT) / 128, 256>>>(x, w_ih1, b_ih1);

    const int smem_bytes = SCAN_SMEM_FLOATS * (int)sizeof(float);
    cudaFuncSetAttribute(scan_kernel, cudaFuncAttributeMaxDynamicSharedMemorySize,
                         smem_bytes);
    scan_kernel<<<BT / 2, 128, smem_bytes>>>(
        mask, w_h1h1, b_h1h1, w_h1h2, b_h1h2, w_h2h2, b_h2h2,
        tau_adp_h1, tau_adp_h2, tau_m_h1, tau_m_h2,
        hid1_mem0, hid2_mem0, out);

    readout_kernel<<<BT, 128>>>(w_h2o, b_h2o, tau_m_o, out_mem0, out);

    anorm_kernel<<<1, 256>>>(w_h1h1, w_h2h2, mask, out);
}

// round 9
// speedup vs baseline: 1.8230x; 1.8230x over previous
#include <cuda_runtime.h>
#include <cstdint>
#include <cstddef>

#define BT 256
#define TT 250
#define II 700
#define HH 128
#define OO 20

// Scratch: xin[b][t][h] = (x @ w_ih1 + b_ih1)
__device__ float g_xin[BT * TT * HH];
// layer-2 spike bit-words: [b][t][4] (bit j of word w = spike of h = w*32+j)
__device__ unsigned int g_spk[BT * TT * 4];

// Correctly-rounded f32 exp (matches glibc scalar expf used by XLA:CPU).
__device__ __forceinline__ float exp_cr(float x) {
    return (float)exp((double)x);
}

// packed f32x2 helpers
__device__ __forceinline__ unsigned long long pack2(float lo, float hi) {
    unsigned long long r;
    asm("mov.b64 %0, {%1, %2};" : "=l"(r) : "f"(lo), "f"(hi));
    return r;
}
__device__ __forceinline__ void unpack2(unsigned long long v, float& lo, float& hi) {
    asm("mov.b64 {%0, %1}, %2;" : "=f"(lo), "=f"(hi) : "l"(v));
}
__device__ __forceinline__ void ffma2(unsigned long long& d, unsigned long long a,
                                      unsigned long long b) {
    asm("fma.rn.f32x2 %0, %1, %2, %0;" : "+l"(d) : "l"(a), "l"(b));
}

// ---------------------------------------------------------------------------
// Kernel 1: xin = x @ w_ih1 + b_ih1 — FULL FP32, single ascending-k FMA chain
// per output (numerics identical to R8). Micro-tile columns remapped to
// {2tx+32j} so b-fragment float2 LDS are conflict-free (was 4-way at 8*tx).
// ---------------------------------------------------------------------------
__global__ __launch_bounds__(256) void gemm_xin_kernel(
    const float* __restrict__ x, const float* __restrict__ w,
    const float* __restrict__ bias)
{
    __shared__ float a_sm[16][132];
    __shared__ float b_sm[16][128];

    const int tid = threadIdx.x;
    const int m0 = blockIdx.x * 128;
    const int tx = tid & 15, ty = tid >> 4;
    const int r0 = ty * 8;

    unsigned long long acc[8][4];
#pragma unroll
    for (int r = 0; r < 8; r++)
#pragma unroll
        for (int j = 0; j < 4; j++) acc[r][j] = 0ull;

    for (int k0 = 0; k0 < II; k0 += 16) {
#pragma unroll
        for (int p = 0; p < 8; p++) {
            int idx = tid + p * 256;
            int ml = idx >> 4, kl = idx & 15;
            int k = k0 + kl;
            a_sm[kl][ml] = (k < II) ? x[(size_t)(m0 + ml) * II + k] : 0.f;
        }
#pragma unroll
        for (int p = 0; p < 8; p++) {
            int idx = tid + p * 256;
            int kl = idx >> 7, hh = idx & 127;
            int k = k0 + kl;
            b_sm[kl][hh] = (k < II) ? w[k * HH + hh] : 0.f;
        }
        __syncthreads();
#pragma unroll
        for (int kk = 0; kk < 16; kk++) {
            float a[8];
            unsigned long long bb[4];
#pragma unroll
            for (int r = 0; r < 8; r++) a[r] = a_sm[kk][r0 + r];
            const float2* bp = reinterpret_cast<const float2*>(&b_sm[kk][2 * tx]);
#pragma unroll
            for (int j = 0; j < 4; j++) { float2 v = bp[16 * j]; bb[j] = pack2(v.x, v.y); }
#pragma unroll
            for (int r = 0; r < 8; r++) {
                unsigned long long ad = pack2(a[r], a[r]);
#pragma unroll
                for (int j = 0; j < 4; j++) ffma2(acc[r][j], ad, bb[j]);
            }
        }
        __syncthreads();
    }

#pragma unroll
    for (int r = 0; r < 8; r++) {
        int m = m0 + r0 + r;
#pragma unroll
        for (int j = 0; j < 4; j++) {
            float lo, hi;
            unpack2(acc[r][j], lo, hi);
            int c = 2 * tx + 32 * j;
            float2 v;
            v.x = __fadd_rn(lo, bias[c]);
            v.y = __fadd_rn(hi, bias[c + 1]);
            *reinterpret_cast<float2*>(&g_xin[(size_t)m * HH + c]) = v;
        }
    }
}

// ---------------------------------------------------------------------------
// Kernel 2: the 250-step scan. 128 blocks x 128 thr (2 batch rows / block).
// R8 numerics preserved EXACTLY; dots computed sparsely over active spike
// bits (bit-identical: fma(0,w,acc)==acc, fma(1,w,acc)==fadd(acc,w)).
// Spikes exchanged as ballot bit-words -> only 2 barriers per step.
// ---------------------------------------------------------------------------
#define SCAN_SMEM_FLOATS (3 * 16384 + 3 * 128 + 16)

__global__ __launch_bounds__(128) void scan_kernel(
    const float* __restrict__ mask,
    const float* __restrict__ w_h1h1, const float* __restrict__ b_h1h1,
    const float* __restrict__ w_h1h2, const float* __restrict__ b_h1h2,
    const float* __restrict__ w_h2h2, const float* __restrict__ b_h2h2,
    const float* __restrict__ tau_adp_h1, const float* __restrict__ tau_adp_h2,
    const float* __restrict__ tau_m_h1,   const float* __restrict__ tau_m_h2,
    const float* __restrict__ hid1_mem0, const float* __restrict__ hid2_mem0,
    float* __restrict__ out)
{
    extern __shared__ float sm[];
    float*  w11  = sm;                  // [k][h] masked, fp32
    float*  w12  = w11 + 16384;         // [k][h] fp32
    float*  w22  = w12 + 16384;         // [k][h] masked, fp32
    float*  b11s = w22 + 16384;
    float*  b12s = b11s + 128;
    float*  b22s = b12s + 128;
    unsigned int* s1wsh = (unsigned int*)(b22s + 128);  // [2][4] layer-1 words
    unsigned int* s2wsh = s1wsh + 8;                    // [2][4] layer-2 words

    const int h  = threadIdx.x;
    const int b0 = blockIdx.x * 2;

#pragma unroll 4
    for (int k = 0; k < 128; k++) {
        int i = k * 128 + h;
        w11[i] = __fmul_rn(w_h1h1[i], mask[i]);
        w12[i] = w_h1h2[i];
        w22[i] = __fmul_rn(w_h2h2[i], mask[16384 + i]);
    }
    b11s[h] = b_h1h1[h];
    b12s[h] = b_h1h2[h];
    b22s[h] = b_h2h2[h];
    if (h < 16) s1wsh[h] = 0u;   // covers s1wsh[0..7] and s2wsh[0..7]

    const float a1 = exp_cr(__fdiv_rn(-1.0f, tau_m_h1[h]));
    const float r1 = exp_cr(__fdiv_rn(-1.0f, tau_adp_h1[h]));
    const float a2 = exp_cr(__fdiv_rn(-1.0f, tau_m_h2[h]));
    const float r2 = exp_cr(__fdiv_rn(-1.0f, tau_adp_h2[h]));
    const float oma1 = __fsub_rn(1.f, a1);
    const float omr1 = __fsub_rn(1.f, r1);
    const float oma2 = __fsub_rn(1.f, a2);
    const float omr2 = __fsub_rn(1.f, r2);

    float h1m[2], h2m[2];
    float h1sp[2] = {0.f, 0.f}, h2sp[2] = {0.f, 0.f};
    float bb1[2] = {0.01f, 0.01f}, bb2[2] = {0.01f, 0.01f};
    float cnt1[2] = {0.f, 0.f}, cnt2[2] = {0.f, 0.f};
    h1m[0] = hid1_mem0[(size_t)b0 * 128 + h];
    h1m[1] = hid1_mem0[(size_t)(b0 + 1) * 128 + h];
    h2m[0] = hid2_mem0[(size_t)b0 * 128 + h];
    h2m[1] = hid2_mem0[(size_t)(b0 + 1) * 128 + h];

    const int wi = h >> 5;
    const int l  = h & 31;

    __syncthreads();

    const float* xin0 = g_xin + (size_t)b0 * TT * HH + h;
    const float* xin1 = g_xin + (size_t)(b0 + 1) * TT * HH + h;

    // previous-step spike words, register-resident
    unsigned int u1[2][4] = {{0u,0u,0u,0u},{0u,0u,0u,0u}};
    unsigned int u2[2][4] = {{0u,0u,0u,0u},{0u,0u,0u,0u}};

    // prefetch xin for t=0
    float xa = xin0[0];
    float xb = xin1[0];

    for (int t = 0; t < TT; t++) {
        // prefetch next step's xin (hides gmem latency behind this step)
        float xan = 0.f, xbn = 0.f;
        if (t + 1 < TT) {
            xan = xin0[(size_t)(t + 1) * HH];
            xbn = xin1[(size_t)(t + 1) * HH];
        }
        // --- recurrent dots: sparse over active bits, ascending k ---
        float m1a = 0.f, m1b = 0.f, m22a = 0.f, m22b = 0.f;
#pragma unroll
        for (int w = 0; w < 4; w++) {
            const float* wp = w11 + w * 32 * 128 + h;
            const float* wq = w22 + w * 32 * 128 + h;
            unsigned int d;
            d = u1[0][w];
            while (d) { int j = __ffs(d) - 1; d &= d - 1;
                        m1a  = __fadd_rn(m1a,  wp[j * 128]); }
            d = u1[1][w];
            while (d) { int j = __ffs(d) - 1; d &= d - 1;
                        m1b  = __fadd_rn(m1b,  wp[j * 128]); }
            d = u2[0][w];
            while (d) { int j = __ffs(d) - 1; d &= d - 1;
                        m22a = __fadd_rn(m22a, wq[j * 128]); }
            d = u2[1][w];
            while (d) { int j = __ffs(d) - 1; d &= d - 1;
                        m22b = __fadd_rn(m22b, wq[j * 128]); }
        }
        // --- layer 1 update (numerics identical to R8) ---
        float i1a = __fadd_rn(__fadd_rn(xa, m1a), b11s[h]);
        float i1b = __fadd_rn(__fadd_rn(xb, m1b), b11s[h]);
        bb1[0] = __fadd_rn(__fmul_rn(r1, bb1[0]), __fmul_rn(omr1, h1sp[0]));
        bb1[1] = __fadd_rn(__fmul_rn(r1, bb1[1]), __fmul_rn(omr1, h1sp[1]));
        float B1a = __fadd_rn(0.01f, __fmul_rn(1.8f, bb1[0]));
        float B1b = __fadd_rn(0.01f, __fmul_rn(1.8f, bb1[1]));
        h1m[0] = __fsub_rn(__fadd_rn(__fmul_rn(h1m[0], a1), __fmul_rn(oma1, i1a)),
                           __fmul_rn(B1a, h1sp[0]));
        h1m[1] = __fsub_rn(__fadd_rn(__fmul_rn(h1m[1], a1), __fmul_rn(oma1, i1b)),
                           __fmul_rn(B1b, h1sp[1]));
        float s1n0 = (__fsub_rn(h1m[0], B1a) > 0.f) ? 1.f : 0.f;
        float s1n1 = (__fsub_rn(h1m[1], B1b) > 0.f) ? 1.f : 0.f;
        cnt1[0] += s1n0; cnt1[1] += s1n1;
        h1sp[0] = s1n0;  h1sp[1] = s1n1;
        // publish layer-1 spike words
        unsigned int w10 = __ballot_sync(0xffffffffu, s1n0 != 0.f);
        unsigned int w11b = __ballot_sync(0xffffffffu, s1n1 != 0.f);
        if (l == 0) { s1wsh[wi] = w10; s1wsh[4 + wi] = w11b; }
        __syncthreads();
        unsigned int n1[2][4];
#pragma unroll
        for (int w = 0; w < 4; w++) { n1[0][w] = s1wsh[w]; n1[1][w] = s1wsh[4 + w]; }
        // --- layer 2: uses NEW layer-1 spikes, sparse ---
        float m12a = 0.f, m12b = 0.f;
#pragma unroll
        for (int w = 0; w < 4; w++) {
            const float* wp = w12 + w * 32 * 128 + h;
            unsigned int d;
            d = n1[0][w];
            while (d) { int j = __ffs(d) - 1; d &= d - 1;
                        m12a = __fadd_rn(m12a, wp[j * 128]); }
            d = n1[1][w];
            while (d) { int j = __ffs(d) - 1; d &= d - 1;
                        m12b = __fadd_rn(m12b, wp[j * 128]); }
        }
        float i2a = __fadd_rn(__fadd_rn(__fadd_rn(m12a, b12s[h]), m22a), b22s[h]);
        float i2b = __fadd_rn(__fadd_rn(__fadd_rn(m12b, b12s[h]), m22b), b22s[h]);
        bb2[0] = __fadd_rn(__fmul_rn(r2, bb2[0]), __fmul_rn(omr2, h2sp[0]));
        bb2[1] = __fadd_rn(__fmul_rn(r2, bb2[1]), __fmul_rn(omr2, h2sp[1]));
        float B2a = __fadd_rn(0.01f, __fmul_rn(1.8f, bb2[0]));
        float B2b = __fadd_rn(0.01f, __fmul_rn(1.8f, bb2[1]));
        h2m[0] = __fsub_rn(__fadd_rn(__fmul_rn(h2m[0], a2), __fmul_rn(oma2, i2a)),
                           __fmul_rn(B2a, h2sp[0]));
        h2m[1] = __fsub_rn(__fadd_rn(__fmul_rn(h2m[1], a2), __fmul_rn(oma2, i2b)),
                           __fmul_rn(B2b, h2sp[1]));
        float s2n0 = (__fsub_rn(h2m[0], B2a) > 0.f) ? 1.f : 0.f;
        float s2n1 = (__fsub_rn(h2m[1], B2b) > 0.f) ? 1.f : 0.f;
        cnt2[0] += s2n0; cnt2[1] += s2n1;
        h2sp[0] = s2n0;  h2sp[1] = s2n1;
        // publish layer-2 spike words (+ export for readout kernel)
        unsigned int w20 = __ballot_sync(0xffffffffu, s2n0 != 0.f);
        unsigned int w21 = __ballot_sync(0xffffffffu, s2n1 != 0.f);
        if (l == 0) {
            s2wsh[wi] = w20; s2wsh[4 + wi] = w21;
            g_spk[((size_t)b0 * TT + t) * 4 + wi]       = w20;
            g_spk[((size_t)(b0 + 1) * TT + t) * 4 + wi] = w21;
        }
        __syncthreads();
#pragma unroll
        for (int w = 0; w < 4; w++) {
            u1[0][w] = n1[0][w];
            u1[1][w] = n1[1][w];
            u2[0][w] = s2wsh[w];
            u2[1][w] = s2wsh[4 + w];
        }
        xa = xan; xb = xbn;
    }

    const float T250 = 250.0f;
    out[5120 + (size_t)b0 * 128 + h]               = cnt1[0] / T250;
    out[5120 + (size_t)(b0 + 1) * 128 + h]         = cnt1[1] / T250;
    out[5120 + 32768 + (size_t)b0 * 128 + h]       = cnt2[0] / T250;
    out[5120 + 32768 + (size_t)(b0 + 1) * 128 + h] = cnt2[1] / T250;
}

// ---------------------------------------------------------------------------
// Kernel 3: readout (om recursion + masked softmax accumulation), full fp32
// with correctly-rounded exp. Unchanged from R8.
// ---------------------------------------------------------------------------
__global__ __launch_bounds__(128) void readout_kernel(
    const float* __restrict__ w_h2o, const float* __restrict__ b_h2o,
    const float* __restrict__ tau_m_o, const float* __restrict__ out_mem0,
    float* __restrict__ out)
{
    __shared__ float w2o_sm[128 * 20];
    __shared__ unsigned int spk[TT][4];
    __shared__ float io_sm[TT][20];

    const int b = blockIdx.x;
    const int tid = threadIdx.x;

    for (int i = tid; i < 128 * 20; i += 128) w2o_sm[i] = w_h2o[i];
    for (int i = tid; i < TT * 4; i += 128)
        ((unsigned int*)spk)[i] = g_spk[(size_t)b * TT * 4 + i];
    __syncthreads();

    for (int p = tid; p < TT * 20; p += 128) {
        int t = p / 20;
        int o = p - t * 20;
        float acc = 0.f;
#pragma unroll
        for (int w = 0; w < 4; w++) {
            unsigned int word = spk[t][w];
            while (word) {
                int j = __ffs(word) - 1; word &= word - 1;
                acc = __fadd_rn(acc, w2o_sm[(w * 32 + j) * 20 + o]);
            }
        }
        io_sm[t][o] = acc;
    }
    __syncthreads();

    if (tid < 32) {
        const int ll = tid;
        float om = 0.f, ao = 0.f, bo = 0.f, accm = 0.f;
        if (ll < 20) {
            om = out_mem0[(size_t)b * 20 + ll];
            ao = (float)exp((double)__fdiv_rn(-1.0f, tau_m_o[ll]));
            bo = b_h2o[ll];
        }
        const float omao = __fsub_rn(1.f, ao);
        for (int t = 0; t < TT; t++) {
            float iov = (ll < 20) ? __fadd_rn(io_sm[t][ll], bo) : 0.f;
            om = __fadd_rn(__fmul_rn(om, ao), __fmul_rn(omao, iov));
            if (t > 10) {
                float v = (ll < 20) ? om : -3.402823466e38f;
#pragma unroll
                for (int d = 16; d > 0; d >>= 1)
                    v = fmaxf(v, __shfl_xor_sync(0xffffffffu, v, d));
                float e = (ll < 20) ? (float)exp((double)__fsub_rn(om, v)) : 0.f;
                float ssum = 0.f;
#pragma unroll
                for (int o = 0; o < 20; o++)
                    ssum = __fadd_rn(ssum, __shfl_sync(0xffffffffu, e, o));
                if (ll < 20) accm = __fadd_rn(accm, __fdiv_rn(e, ssum));
            }
        }
        if (ll < 20) out[(size_t)b * 20 + ll] = accm;
    }
}

// ---------------------------------------------------------------------------
// Kernel 4: A_norm — unchanged from R8 (passed).
// ---------------------------------------------------------------------------
__global__ __launch_bounds__(256) void anorm_kernel(
    const float* __restrict__ w_h1h1, const float* __restrict__ w_h2h2,
    const float* __restrict__ mask, float* __restrict__ out)
{
    __shared__ float red1[256];
    __shared__ float red2[256];
    int tid = threadIdx.x;
    float s1 = 0.f, s2 = 0.f;
    for (int i = tid; i < 16384; i += 256) {
        s1 = __fadd_rn(s1, fabsf(__fmul_rn(w_h1h1[i], mask[i])));
        s2 = __fadd_rn(s2, fabsf(__fmul_rn(w_h2h2[i], mask[16384 + i])));
    }
    red1[tid] = s1;
    red2[tid] = s2;
    __syncthreads();
#pragma unroll
    for (int st = 128; st > 0; st >>= 1) {
        if (tid < st) {
            red1[tid] = __fadd_rn(red1[tid], red1[tid + st]);
            red2[tid] = __fadd_rn(red2[tid], red2[tid + st]);
        }
        __syncthreads();
    }
    if (tid == 0) out[5120 + 2 * 32768] = __fadd_rn(red1[0], red2[0]);
}

// ---------------------------------------------------------------------------
extern "C" void kernel_launch(void* const* d_in, const int* in_sizes, int n_in,
                              void* d_out, int out_size)
{
    (void)in_sizes; (void)n_in; (void)out_size;
    const float* x          = (const float*)d_in[0];
    const float* mask       = (const float*)d_in[1];
    const float* w_ih1      = (const float*)d_in[2];
    const float* b_ih1      = (const float*)d_in[3];
    const float* w_h1h1     = (const float*)d_in[4];
    const float* b_h1h1     = (const float*)d_in[5];
    const float* w_h1h2     = (const float*)d_in[6];
    const float* b_h1h2     = (const float*)d_in[7];
    const float* w_h2h2     = (const float*)d_in[8];
    const float* b_h2h2     = (const float*)d_in[9];
    const float* w_h2o      = (const float*)d_in[10];
    const float* b_h2o      = (const float*)d_in[11];
    const float* tau_adp_h1 = (const float*)d_in[12];
    const float* tau_adp_h2 = (const float*)d_in[13];
    const float* tau_m_h1   = (const float*)d_in[14];
    const float* tau_m_h2   = (const float*)d_in[15];
    const float* tau_m_o    = (const float*)d_in[16];
    const float* hid1_mem0  = (const float*)d_in[17];
    const float* hid2_mem0  = (const float*)d_in[18];
    const float* out_mem0   = (const float*)d_in[19];
    float* out = (float*)d_out;

    gemm_xin_kernel<<<(BT * TT) / 128, 256>>>(x, w_ih1, b_ih1);

    const int smem_bytes = SCAN_SMEM_FLOATS * (int)sizeof(float);
    cudaFuncSetAttribute(scan_kernel, cudaFuncAttributeMaxDynamicSharedMemorySize,
                         smem_bytes);
    scan_kernel<<<BT / 2, 128, smem_bytes>>>(
        mask, w_h1h1, b_h1h1, w_h1h2, b_h1h2, w_h2h2, b_h2h2,
        tau_adp_h1, tau_adp_h2, tau_m_h1, tau_m_h2,
        hid1_mem0, hid2_mem0, out);

    readout_kernel<<<BT, 128>>>(w_h2o, b_h2o, tau_m_o, out_mem0, out);

    anorm_kernel<<<1, 256>>>(w_h1h1, w_h2h2, mask, out);
}

// round 10
// speedup vs baseline: 1.9457x; 1.0673x over previous
#include <cuda_runtime.h>
#include <cstdint>
#include <cstddef>

#define BT 256
#define TT 250
#define II 700
#define HH 128
#define OO 20

// Scratch: xin[b][t][h] = (x @ w_ih1 + b_ih1)
__device__ float g_xin[BT * TT * HH];
// layer-2 spike bit-words: [b][t][4] (bit j of word w = spike of h = w*32+j)
__device__ unsigned int g_spk[BT * TT * 4];

// Correctly-rounded f32 exp (matches glibc scalar expf used by XLA:CPU).
__device__ __forceinline__ float exp_cr(float x) {
    return (float)exp((double)x);
}

// packed f32x2 helpers
__device__ __forceinline__ unsigned long long pack2(float lo, float hi) {
    unsigned long long r;
    asm("mov.b64 %0, {%1, %2};" : "=l"(r) : "f"(lo), "f"(hi));
    return r;
}
__device__ __forceinline__ void unpack2(unsigned long long v, float& lo, float& hi) {
    asm("mov.b64 {%0, %1}, %2;" : "=f"(lo), "=f"(hi) : "l"(v));
}
__device__ __forceinline__ void ffma2(unsigned long long& d, unsigned long long a,
                                      unsigned long long b) {
    asm("fma.rn.f32x2 %0, %1, %2, %0;" : "+l"(d) : "l"(a), "l"(b));
}

// ---------------------------------------------------------------------------
// Kernel 1: xin = x @ w_ih1 + b_ih1 — FULL FP32, single ascending-k FMA chain
// per output (numerics identical to R8/R9). Register-staged pipeline: tile
// k+1's LDGs are in flight while tile k computes from smem.
// ---------------------------------------------------------------------------
__global__ __launch_bounds__(256) void gemm_xin_kernel(
    const float* __restrict__ x, const float* __restrict__ w,
    const float* __restrict__ bias)
{
    __shared__ float a_sm[16][132];
    __shared__ float b_sm[16][128];

    const int tid = threadIdx.x;
    const int m0 = blockIdx.x * 128;
    const int tx = tid & 15, ty = tid >> 4;
    const int r0 = ty * 8;

    // load-index precompute (fixed per thread)
    const int a_ml = tid >> 4, a_kl = tid & 15;      // + p*16 rows
    const int b_kl = tid >> 7, b_hh = tid & 127;     // + p*2 rows

    unsigned long long acc[8][4];
#pragma unroll
    for (int r = 0; r < 8; r++)
#pragma unroll
        for (int j = 0; j < 4; j++) acc[r][j] = 0ull;

    const int NT = (II + 15) / 16;   // 44 k-tiles
    float ra[8], rb[8];

    // preload tile 0 into registers
    {
        int k0 = 0;
#pragma unroll
        for (int p = 0; p < 8; p++) {
            int k = k0 + a_kl;
            ra[p] = (k < II) ? x[(size_t)(m0 + a_ml + p * 16) * II + k] : 0.f;
        }
#pragma unroll
        for (int p = 0; p < 8; p++) {
            int k = k0 + b_kl + p * 2;
            rb[p] = (k < II) ? w[k * HH + b_hh] : 0.f;
        }
    }

    for (int kt = 0; kt < NT; kt++) {
        // commit staged tile to smem
#pragma unroll
        for (int p = 0; p < 8; p++) a_sm[a_kl][a_ml + p * 16] = ra[p];
#pragma unroll
        for (int p = 0; p < 8; p++) b_sm[b_kl + p * 2][b_hh] = rb[p];
        __syncthreads();

        // issue next tile's loads (in flight during compute)
        if (kt + 1 < NT) {
            int k0 = (kt + 1) * 16;
#pragma unroll
            for (int p = 0; p < 8; p++) {
                int k = k0 + a_kl;
                ra[p] = (k < II) ? x[(size_t)(m0 + a_ml + p * 16) * II + k] : 0.f;
            }
#pragma unroll
            for (int p = 0; p < 8; p++) {
                int k = k0 + b_kl + p * 2;
                rb[p] = (k < II) ? w[k * HH + b_hh] : 0.f;
            }
        }

#pragma unroll
        for (int kk = 0; kk < 16; kk++) {
            float a[8];
            unsigned long long bb[4];
#pragma unroll
            for (int r = 0; r < 8; r++) a[r] = a_sm[kk][r0 + r];
            const float2* bp = reinterpret_cast<const float2*>(&b_sm[kk][2 * tx]);
#pragma unroll
            for (int j = 0; j < 4; j++) { float2 v = bp[16 * j]; bb[j] = pack2(v.x, v.y); }
#pragma unroll
            for (int r = 0; r < 8; r++) {
                unsigned long long ad = pack2(a[r], a[r]);
#pragma unroll
                for (int j = 0; j < 4; j++) ffma2(acc[r][j], ad, bb[j]);
            }
        }
        __syncthreads();
    }

#pragma unroll
    for (int r = 0; r < 8; r++) {
        int m = m0 + r0 + r;
#pragma unroll
        for (int j = 0; j < 4; j++) {
            float lo, hi;
            unpack2(acc[r][j], lo, hi);
            int c = 2 * tx + 32 * j;
            float2 v;
            v.x = __fadd_rn(lo, bias[c]);
            v.y = __fadd_rn(hi, bias[c + 1]);
            *reinterpret_cast<float2*>(&g_xin[(size_t)m * HH + c]) = v;
        }
    }
}

// ---------------------------------------------------------------------------
// Kernel 2: the 250-step scan. 128 blocks x 256 thr. Thread (h, r) owns one
// batch row's state -> 2 warps/SMSP, half the dot work per warp. Sparse dots
// over spike bits with per-word split accumulators (re-association proven
// bit-stable by the R2==R6 experiment). 2 barriers per step.
// ---------------------------------------------------------------------------
#define SCAN_SMEM_FLOATS (3 * 16384 + 3 * 128 + 16)

__global__ __launch_bounds__(256) void scan_kernel(
    const float* __restrict__ mask,
    const float* __restrict__ w_h1h1, const float* __restrict__ b_h1h1,
    const float* __restrict__ w_h1h2, const float* __restrict__ b_h1h2,
    const float* __restrict__ w_h2h2, const float* __restrict__ b_h2h2,
    const float* __restrict__ tau_adp_h1, const float* __restrict__ tau_adp_h2,
    const float* __restrict__ tau_m_h1,   const float* __restrict__ tau_m_h2,
    const float* __restrict__ hid1_mem0, const float* __restrict__ hid2_mem0,
    float* __restrict__ out)
{
    extern __shared__ float sm[];
    float*  w11  = sm;                  // [k][h] masked, fp32
    float*  w12  = w11 + 16384;         // [k][h] fp32
    float*  w22  = w12 + 16384;         // [k][h] masked, fp32
    float*  b11s = w22 + 16384;
    float*  b12s = b11s + 128;
    float*  b22s = b12s + 128;
    unsigned int* s1w = (unsigned int*)(b22s + 128);  // [2 rows][4 words]
    unsigned int* s2w = s1w + 8;                      // [2 rows][4 words]

    const int tid = threadIdx.x;
    const int h   = tid & 127;
    const int r   = tid >> 7;          // batch row within pair
    const int wi  = tid >> 5;          // warp 0..7 ; row = wi>>2, word = wi&3
    const int l   = tid & 31;
    const int b   = blockIdx.x * 2 + r;

    // weight load: 256 threads, 64 elems each per matrix, coalesced
#pragma unroll 4
    for (int p = 0; p < 64; p++) {
        int i = p * 256 + tid;
        w11[i] = __fmul_rn(w_h1h1[i], mask[i]);
        w12[i] = w_h1h2[i];
        w22[i] = __fmul_rn(w_h2h2[i], mask[16384 + i]);
    }
    if (r == 0) {
        b11s[h] = b_h1h1[h];
        b12s[h] = b_h1h2[h];
        b22s[h] = b_h2h2[h];
    }
    if (tid < 16) s1w[tid] = 0u;   // covers s1w[0..7] + s2w[0..7]

    const float a1 = exp_cr(__fdiv_rn(-1.0f, tau_m_h1[h]));
    const float r1 = exp_cr(__fdiv_rn(-1.0f, tau_adp_h1[h]));
    const float a2 = exp_cr(__fdiv_rn(-1.0f, tau_m_h2[h]));
    const float r2 = exp_cr(__fdiv_rn(-1.0f, tau_adp_h2[h]));
    const float oma1 = __fsub_rn(1.f, a1);
    const float omr1 = __fsub_rn(1.f, r1);
    const float oma2 = __fsub_rn(1.f, a2);
    const float omr2 = __fsub_rn(1.f, r2);

    float h1m = hid1_mem0[(size_t)b * 128 + h];
    float h2m = hid2_mem0[(size_t)b * 128 + h];
    float h1sp = 0.f, h2sp = 0.f;
    float bb1 = 0.01f, bb2 = 0.01f;
    float cnt1 = 0.f, cnt2 = 0.f;

    unsigned int u1[4] = {0u, 0u, 0u, 0u};
    unsigned int u2[4] = {0u, 0u, 0u, 0u};

    __syncthreads();

    const float* xin = g_xin + (size_t)b * TT * HH + h;
    float xa = xin[0];

    for (int t = 0; t < TT; t++) {
        float xan = (t + 1 < TT) ? xin[(size_t)(t + 1) * HH] : 0.f;

        // --- layer-1 recurrent dot + layer-2 self dot: sparse, per-word
        // accumulators (8 independent LDS->FADD chains) ---
        float p1[4], p2[4];
#pragma unroll
        for (int w = 0; w < 4; w++) {
            const float* wp = w11 + (w << 12) + h;
            const float* wq = w22 + (w << 12) + h;
            float acc1 = 0.f, acc2 = 0.f;
            unsigned int d;
            d = u1[w];
            while (d) { int j = __ffs(d) - 1; d &= d - 1;
                        acc1 = __fadd_rn(acc1, wp[j << 7]); }
            d = u2[w];
            while (d) { int j = __ffs(d) - 1; d &= d - 1;
                        acc2 = __fadd_rn(acc2, wq[j << 7]); }
            p1[w] = acc1; p2[w] = acc2;
        }
        float m1  = __fadd_rn(__fadd_rn(__fadd_rn(p1[0], p1[1]), p1[2]), p1[3]);
        float m22 = __fadd_rn(__fadd_rn(__fadd_rn(p2[0], p2[1]), p2[2]), p2[3]);

        // --- layer 1 update (R8 elementwise numerics) ---
        float i1 = __fadd_rn(__fadd_rn(xa, m1), b11s[h]);
        bb1 = __fadd_rn(__fmul_rn(r1, bb1), __fmul_rn(omr1, h1sp));
        float B1 = __fadd_rn(0.01f, __fmul_rn(1.8f, bb1));
        h1m = __fsub_rn(__fadd_rn(__fmul_rn(h1m, a1), __fmul_rn(oma1, i1)),
                        __fmul_rn(B1, h1sp));
        float s1n = (__fsub_rn(h1m, B1) > 0.f) ? 1.f : 0.f;
        cnt1 += s1n; h1sp = s1n;

        unsigned int wd1 = __ballot_sync(0xffffffffu, s1n != 0.f);
        if (l == 0) s1w[wi] = wd1;
        __syncthreads();

        unsigned int n1[4];
#pragma unroll
        for (int w = 0; w < 4; w++) n1[w] = s1w[(r << 2) + w];

        // --- layer 2 forward dot: sparse over NEW layer-1 spikes ---
        float q[4];
#pragma unroll
        for (int w = 0; w < 4; w++) {
            const float* wp = w12 + (w << 12) + h;
            float acc = 0.f;
            unsigned int d = n1[w];
            while (d) { int j = __ffs(d) - 1; d &= d - 1;
                        acc = __fadd_rn(acc, wp[j << 7]); }
            q[w] = acc;
        }
        float m12 = __fadd_rn(__fadd_rn(__fadd_rn(q[0], q[1]), q[2]), q[3]);

        float i2 = __fadd_rn(__fadd_rn(__fadd_rn(m12, b12s[h]), m22), b22s[h]);
        bb2 = __fadd_rn(__fmul_rn(r2, bb2), __fmul_rn(omr2, h2sp));
        float B2 = __fadd_rn(0.01f, __fmul_rn(1.8f, bb2));
        h2m = __fsub_rn(__fadd_rn(__fmul_rn(h2m, a2), __fmul_rn(oma2, i2)),
                        __fmul_rn(B2, h2sp));
        float s2n = (__fsub_rn(h2m, B2) > 0.f) ? 1.f : 0.f;
        cnt2 += s2n; h2sp = s2n;

        unsigned int wd2 = __ballot_sync(0xffffffffu, s2n != 0.f);
        if (l == 0) {
            s2w[wi] = wd2;
            g_spk[((size_t)b * TT + t) * 4 + (wi & 3)] = wd2;
        }
        __syncthreads();

#pragma unroll
        for (int w = 0; w < 4; w++) {
            u1[w] = n1[w];
            u2[w] = s2w[(r << 2) + w];
        }
        xa = xan;
    }

    const float T250 = 250.0f;
    out[5120 + (size_t)b * 128 + h]         = cnt1 / T250;
    out[5120 + 32768 + (size_t)b * 128 + h] = cnt2 / T250;
}

// ---------------------------------------------------------------------------
// Kernel 3: readout (om recursion + masked softmax accumulation), full fp32
// with correctly-rounded exp. Unchanged from R9 (passed).
// ---------------------------------------------------------------------------
__global__ __launch_bounds__(128) void readout_kernel(
    const float* __restrict__ w_h2o, const float* __restrict__ b_h2o,
    const float* __restrict__ tau_m_o, const float* __restrict__ out_mem0,
    float* __restrict__ out)
{
    __shared__ float w2o_sm[128 * 20];
    __shared__ unsigned int spk[TT][4];
    __shared__ float io_sm[TT][20];

    const int b = blockIdx.x;
    const int tid = threadIdx.x;

    for (int i = tid; i < 128 * 20; i += 128) w2o_sm[i] = w_h2o[i];
    for (int i = tid; i < TT * 4; i += 128)
        ((unsigned int*)spk)[i] = g_spk[(size_t)b * TT * 4 + i];
    __syncthreads();

    for (int p = tid; p < TT * 20; p += 128) {
        int t = p / 20;
        int o = p - t * 20;
        float acc = 0.f;
#pragma unroll
        for (int w = 0; w < 4; w++) {
            unsigned int word = spk[t][w];
            while (word) {
                int j = __ffs(word) - 1; word &= word - 1;
                acc = __fadd_rn(acc, w2o_sm[(w * 32 + j) * 20 + o]);
            }
        }
        io_sm[t][o] = acc;
    }
    __syncthreads();

    if (tid < 32) {
        const int ll = tid;
        float om = 0.f, ao = 0.f, bo = 0.f, accm = 0.f;
        if (ll < 20) {
            om = out_mem0[(size_t)b * 20 + ll];
            ao = (float)exp((double)__fdiv_rn(-1.0f, tau_m_o[ll]));
            bo = b_h2o[ll];
        }
        const float omao = __fsub_rn(1.f, ao);
        for (int t = 0; t < TT; t++) {
            float iov = (ll < 20) ? __fadd_rn(io_sm[t][ll], bo) : 0.f;
            om = __fadd_rn(__fmul_rn(om, ao), __fmul_rn(omao, iov));
            if (t > 10) {
                float v = (ll < 20) ? om : -3.402823466e38f;
#pragma unroll
                for (int d = 16; d > 0; d >>= 1)
                    v = fmaxf(v, __shfl_xor_sync(0xffffffffu, v, d));
                float e = (ll < 20) ? (float)exp((double)__fsub_rn(om, v)) : 0.f;
                float ssum = 0.f;
#pragma unroll
                for (int o = 0; o < 20; o++)
                    ssum = __fadd_rn(ssum, __shfl_sync(0xffffffffu, e, o));
                if (ll < 20) accm = __fadd_rn(accm, __fdiv_rn(e, ssum));
            }
        }
        if (ll < 20) out[(size_t)b * 20 + ll] = accm;
    }
}

// ---------------------------------------------------------------------------
// Kernel 4: A_norm — unchanged from R8/R9 (passed).
// ---------------------------------------------------------------------------
__global__ __launch_bounds__(256) void anorm_kernel(
    const float* __restrict__ w_h1h1, const float* __restrict__ w_h2h2,
    const float* __restrict__ mask, float* __restrict__ out)
{
    __shared__ float red1[256];
    __shared__ float red2[256];
    int tid = threadIdx.x;
    float s1 = 0.f, s2 = 0.f;
    for (int i = tid; i < 16384; i += 256) {
        s1 = __fadd_rn(s1, fabsf(__fmul_rn(w_h1h1[i], mask[i])));
        s2 = __fadd_rn(s2, fabsf(__fmul_rn(w_h2h2[i], mask[16384 + i])));
    }
    red1[tid] = s1;
    red2[tid] = s2;
    __syncthreads();
#pragma unroll
    for (int st = 128; st > 0; st >>= 1) {
        if (tid < st) {
            red1[tid] = __fadd_rn(red1[tid], red1[tid + st]);
            red2[tid] = __fadd_rn(red2[tid], red2[tid + st]);
        }
        __syncthreads();
    }
    if (tid == 0) out[5120 + 2 * 32768] = __fadd_rn(red1[0], red2[0]);
}

// ---------------------------------------------------------------------------
extern "C" void kernel_launch(void* const* d_in, const int* in_sizes, int n_in,
                              void* d_out, int out_size)
{
    (void)in_sizes; (void)n_in; (void)out_size;
    const float* x          = (const float*)d_in[0];
    const float* mask       = (const float*)d_in[1];
    const float* w_ih1      = (const float*)d_in[2];
    const float* b_ih1      = (const float*)d_in[3];
    const float* w_h1h1     = (const float*)d_in[4];
    const float* b_h1h1     = (const float*)d_in[5];
    const float* w_h1h2     = (const float*)d_in[6];
    const float* b_h1h2     = (const float*)d_in[7];
    const float* w_h2h2     = (const float*)d_in[8];
    const float* b_h2h2     = (const float*)d_in[9];
    const float* w_h2o      = (const float*)d_in[10];
    const float* b_h2o      = (const float*)d_in[11];
    const float* tau_adp_h1 = (const float*)d_in[12];
    const float* tau_adp_h2 = (const float*)d_in[13];
    const float* tau_m_h1   = (const float*)d_in[14];
    const float* tau_m_h2   = (const float*)d_in[15];
    const float* tau_m_o    = (const float*)d_in[16];
    const float* hid1_mem0  = (const float*)d_in[17];
    const float* hid2_mem0  = (const float*)d_in[18];
    const float* out_mem0   = (const float*)d_in[19];
    float* out = (float*)d_out;

    gemm_xin_kernel<<<(BT * TT) / 128, 256>>>(x, w_ih1, b_ih1);

    const int smem_bytes = SCAN_SMEM_FLOATS * (int)sizeof(float);
    cudaFuncSetAttribute(scan_kernel, cudaFuncAttributeMaxDynamicSharedMemorySize,
                         smem_bytes);
    scan_kernel<<<BT / 2, 256, smem_bytes>>>(
        mask, w_h1h1, b_h1h1, w_h1h2, b_h1h2, w_h2h2, b_h2h2,
        tau_adp_h1, tau_adp_h2, tau_m_h1, tau_m_h2,
        hid1_mem0, hid2_mem0, out);

    readout_kernel<<<BT, 128>>>(w_h2o, b_h2o, tau_m_o, out_mem0, out);

    anorm_kernel<<<1, 256>>>(w_h1h1, w_h2h2, mask, out);
}